// round 15
// baseline (speedup 1.0000x reference)
#include <cuda_runtime.h>
#include <cuda_bf16.h>
#include <cuda_fp16.h>
#include <cstdint>

#define SEQ 2048
#define DMODEL 2048
#define NHQ 16
#define NHKV 4
#define DHEAD 128
#define WIN 512

#define QKV_COLS 3072
#define K_OFF 4194304   // 2048*2048
#define V_OFF 5242880   // + 4*2048*128

#define QSCALE (0.08838834764831845f * 1.4426950408889634f)  // 1/sqrt(128) * log2(e)

// ---------------------------------------------------------------------------
// Scratch (device globals; 16B-aligned)
// ---------------------------------------------------------------------------
__device__ __align__(16) __half g_xh[SEQ * DMODEL];         // x in fp16
__device__ __align__(16) __half g_wt[QKV_COLS * DMODEL];    // [Wq^T;Wk^T;Wv^T], fp16
__device__ __align__(16) __half g_wo[DMODEL * DMODEL];      // Wo^T, fp16
__device__ __align__(16) __half g_a_hi[SEQ * DMODEL];       // attention output (fp16)
// attention operands (fp16)
__device__ __align__(16) __half g_qh[NHQ * SEQ * DHEAD];    // [h][s][d], scaled
__device__ __align__(16) __half g_kh[NHKV * SEQ * DHEAD];   // [kvh][s][d]
__device__ __align__(16) __half g_vt[NHKV * DHEAD * SEQ];   // [kvh][d][s]

// ---------------------------------------------------------------------------
// mma.sync helpers (baseline sm_80+ PTX)
// ---------------------------------------------------------------------------
__device__ __forceinline__ uint32_t smem_u32(const void* p) {
    uint32_t a;
    asm("{ .reg .u64 t; cvta.to.shared.u64 t, %1; cvt.u32.u64 %0, t; }" : "=r"(a) : "l"(p));
    return a;
}
__device__ __forceinline__ void ldsm_x4(uint32_t* r, uint32_t a) {
    asm volatile("ldmatrix.sync.aligned.m8n8.x4.shared.b16 {%0,%1,%2,%3}, [%4];"
                 : "=r"(r[0]), "=r"(r[1]), "=r"(r[2]), "=r"(r[3]) : "r"(a));
}
__device__ __forceinline__ void ldsm_x2(uint32_t* r, uint32_t a) {
    asm volatile("ldmatrix.sync.aligned.m8n8.x2.shared.b16 {%0,%1}, [%2];"
                 : "=r"(r[0]), "=r"(r[1]) : "r"(a));
}
__device__ __forceinline__ void mma_f16(float* c, const uint32_t* a, const uint32_t* b) {
    asm volatile(
        "mma.sync.aligned.m16n8k16.row.col.f32.f16.f16.f32 "
        "{%0,%1,%2,%3}, {%4,%5,%6,%7}, {%8,%9}, {%0,%1,%2,%3};"
        : "+f"(c[0]), "+f"(c[1]), "+f"(c[2]), "+f"(c[3])
        : "r"(a[0]), "r"(a[1]), "r"(a[2]), "r"(a[3]), "r"(b[0]), "r"(b[1]));
}
#define CP_ASYNC16(s, g) \
    asm volatile("cp.async.cg.shared.global [%0], [%1], 16;" :: "r"(s), "l"(g))
#define CP_COMMIT() asm volatile("cp.async.commit_group;" ::: "memory")
#define CP_WAIT(n)  asm volatile("cp.async.wait_group %0;" :: "n"(n) : "memory")

// ---------------------------------------------------------------------------
// fp32 -> fp16 convert (elementwise)
// ---------------------------------------------------------------------------
__global__ __launch_bounds__(256) void econv(
    const float4* __restrict__ A, __half* __restrict__ out, int n4)
{
    int i = blockIdx.x * 256 + threadIdx.x;
    if (i >= n4) return;
    float4 v = A[i];
    __half2 a = __float22half2_rn(make_float2(v.x, v.y));
    __half2 b = __float22half2_rn(make_float2(v.z, v.w));
    *(uint32_t*)&out[4 * i]     = *(uint32_t*)&a;
    *(uint32_t*)&out[4 * i + 2] = *(uint32_t*)&b;
}

// ---------------------------------------------------------------------------
// Batched transpose to fp16: all four weights in one launch.
// ---------------------------------------------------------------------------
__global__ __launch_bounds__(256) void ttrans_all(
    const float* __restrict__ Wq, const float* __restrict__ Wk,
    const float* __restrict__ Wv, const float* __restrict__ Wo,
    __half* __restrict__ wt, __half* __restrict__ wo)
{
    __shared__ float t[32][33];
    int tx = threadIdx.x, ty = threadIdx.y;
    int bx = blockIdx.x;

    const float* W; __half* T; int N; int nb;
    if (bx < 64)       { W = Wq; T = wt;               N = 2048; nb = bx; }
    else if (bx < 80)  { W = Wk; T = wt + 2048 * 2048; N = 512;  nb = bx - 64; }
    else if (bx < 96)  { W = Wv; T = wt + 2560 * 2048; N = 512;  nb = bx - 80; }
    else               { W = Wo; T = wo;               N = 2048; nb = bx - 96; }

    int n0 = nb * 32, k0 = blockIdx.y * 32;
#pragma unroll
    for (int i = 0; i < 4; i++)
        t[ty + 8 * i][tx] = W[(size_t)(k0 + ty + 8 * i) * N + n0 + tx];
    __syncthreads();
#pragma unroll
    for (int i = 0; i < 4; i++)
        T[(size_t)(n0 + ty + 8 * i) * 2048 + k0 + tx] = __float2half(t[tx][ty + 8 * i]);
}

// ---------------------------------------------------------------------------
// GEMM mainloop: CTA 128x128, 128 threads, 4 warps in 2x2 grid, warp tile
// 64x64 (1.0 ldsm-matrix per MMA vs 1.5 at 64x32). KC=64, stride 72 halves,
// 2-stage cp.async pipeline. B loaded as paired-j ldsm_x4.
// ---------------------------------------------------------------------------
#define KC 64
#define NCHUNK (2048 / KC)
#define TILE_B 18432          // 128 rows * 72 halves * 2B
#define STAGE1_B (2 * TILE_B)
#define GS1_SMEM (2 * STAGE1_B)   // 73728 B (>= 128*130*4 = 66560 epilogue tile)

#define GEMM_MAINLOOP(Aptr, Bptr)                                              \
    float acc[4][8][4];                                                        \
    _Pragma("unroll")                                                          \
    for (int i = 0; i < 4; i++)                                                \
        _Pragma("unroll")                                                      \
        for (int j = 0; j < 8; j++)                                            \
            _Pragma("unroll")                                                  \
            for (int e = 0; e < 4; e++) acc[i][j][e] = 0.f;                    \
    auto load_chunk = [&](int c, int buf) {                                    \
        const int k0 = c * KC;                                                 \
        const uint32_t st = sbase + buf * STAGE1_B;                            \
        _Pragma("unroll")                                                      \
        for (int i = 0; i < 8; i++) {                                          \
            int op = t + 128 * i;                                              \
            int r = op >> 3, ch = op & 7;                                      \
            uint32_t so = (uint32_t)(r * 144 + ch * 16);                       \
            const size_t go = (size_t)r * 2048 + k0 + ch * 8;                  \
            CP_ASYNC16(st + so, (Aptr) + (size_t)m0 * 2048 + go);              \
            CP_ASYNC16(st + TILE_B + so, (Bptr) + (size_t)n0 * 2048 + go);     \
        }                                                                      \
    };                                                                         \
    load_chunk(0, 0);                                                          \
    CP_COMMIT();                                                               \
    for (int c = 0; c < NCHUNK; c++) {                                         \
        const int buf = c & 1;                                                 \
        if (c + 1 < NCHUNK) { load_chunk(c + 1, (c + 1) & 1); CP_COMMIT(); CP_WAIT(1); } \
        else { CP_WAIT(0); }                                                   \
        __syncthreads();                                                       \
        const uint32_t sA = sbase + buf * STAGE1_B;                            \
        const uint32_t sB = sA + TILE_B;                                       \
        const int arow = mwb + (lane & 15);                                    \
        const int brow = nwb + 8 * ((lane >> 4) & 1) + (lane & 7);             \
        _Pragma("unroll")                                                      \
        for (int ks = 0; ks < 4; ks++) {                                       \
            const int kc = ks * 2;                                             \
            uint32_t af[4][4], bf4[4][4];                                      \
            const int ach = kc + (lane >> 4);                                  \
            const int bch = kc + ((lane >> 3) & 1);                            \
            _Pragma("unroll")                                                  \
            for (int i = 0; i < 4; i++)                                        \
                ldsm_x4(af[i], sA + (uint32_t)((arow + i * 16) * 144 + ach * 16)); \
            _Pragma("unroll")                                                  \
            for (int jj = 0; jj < 4; jj++)                                     \
                ldsm_x4(bf4[jj], sB + (uint32_t)((brow + jj * 16) * 144 + bch * 16)); \
            _Pragma("unroll")                                                  \
            for (int i = 0; i < 4; i++)                                        \
                _Pragma("unroll")                                              \
                for (int jj = 0; jj < 4; jj++) {                               \
                    mma_f16(acc[i][2 * jj],     af[i], &bf4[jj][0]);           \
                    mma_f16(acc[i][2 * jj + 1], af[i], &bf4[jj][2]);           \
                }                                                              \
        }                                                                      \
        __syncthreads();                                                       \
    }

// ---------------------------------------------------------------------------
// QKV GEMM with fused RoPE + scatter epilogue. Grid (24, 16), 128 threads.
// ---------------------------------------------------------------------------
__global__ __launch_bounds__(128, 2) void gemm_qkv(
    const __half* __restrict__ A, const __half* __restrict__ Bw,
    const float* __restrict__ cosc, const float* __restrict__ sinc,
    float* __restrict__ out)
{
    extern __shared__ __align__(16) char sm[];
    const uint32_t sbase = smem_u32(sm);
    const int t = threadIdx.x;
    const int warp = t >> 5, lane = t & 31;
    const int mwb = (warp & 1) * 64;
    const int nwb = (warp >> 1) * 64;
    const int m0 = blockIdx.y * 128, n0 = blockIdx.x * 128;

    GEMM_MAINLOOP(A, Bw)

    // stage fp32 tile in smem, stride 130 floats
    float* ts = (float*)sm;
    const int rq = lane >> 2, cq = (lane & 3) * 2;
#pragma unroll
    for (int i = 0; i < 4; i++) {
#pragma unroll
        for (int j = 0; j < 8; j++) {
            int row = mwb + i * 16 + rq;
            int col = nwb + j * 8 + cq;
            *(float2*)&ts[row * 130 + col] = make_float2(acc[i][j][0], acc[i][j][1]);
            *(float2*)&ts[(row + 8) * 130 + col] = make_float2(acc[i][j][2], acc[i][j][3]);
        }
    }
    __syncthreads();

    if (n0 < 2048) {
        const int h = n0 >> 7;
        for (int e = t; e < 128 * 128; e += 128) {
            int r = e >> 7, d = e & 127;
            int s = m0 + r;
            float v = ts[r * 130 + d];
            float pr = ts[r * 130 + (d ^ 64)];
            float rot = (d < 64) ? -pr : pr;
            float q = (v * cosc[s * DHEAD + d] + rot * sinc[s * DHEAD + d]) * QSCALE;
            g_qh[((size_t)h * SEQ + s) * DHEAD + d] = __float2half(q);
        }
    } else if (n0 < 2560) {
        const int kvh = (n0 - 2048) >> 7;
        for (int e = t; e < 128 * 128; e += 128) {
            int r = e >> 7, d = e & 127;
            int s = m0 + r;
            float v = ts[r * 130 + d];
            float pr = ts[r * 130 + (d ^ 64)];
            float rot = (d < 64) ? -pr : pr;
            float rv = v * cosc[s * DHEAD + d] + rot * sinc[s * DHEAD + d];
            size_t o = ((size_t)kvh * SEQ + s) * DHEAD + d;
            out[K_OFF + o] = rv;
            g_kh[o] = __float2half(rv);
        }
    } else {
        const int kvh = (n0 - 2560) >> 7;
        for (int e = t; e < 128 * 128; e += 128) {
            int r = e >> 7, d = e & 127;
            out[V_OFF + ((size_t)kvh * SEQ + m0 + r) * DHEAD + d] = ts[r * 130 + d];
        }
        for (int e = t; e < 128 * 128; e += 128) {
            int d = e >> 7, sl = e & 127;
            g_vt[((size_t)kvh * DHEAD + d) * SEQ + m0 + sl] =
                __float2half(ts[sl * 130 + d]);
        }
    }
}

// ---------------------------------------------------------------------------
// Plain single-pass fp16 GEMM (Wo projection), 128 threads.
// ---------------------------------------------------------------------------
__global__ __launch_bounds__(128, 2) void gemm_mma1(
    const __half* __restrict__ A, const __half* __restrict__ B,
    float* __restrict__ C, int ldc)
{
    extern __shared__ __align__(16) char sm[];
    const uint32_t sbase = smem_u32(sm);
    const int t = threadIdx.x;
    const int warp = t >> 5, lane = t & 31;
    const int mwb = (warp & 1) * 64;
    const int nwb = (warp >> 1) * 64;
    const int m0 = blockIdx.y * 128, n0 = blockIdx.x * 128;

    GEMM_MAINLOOP(A, B)

    const int rq = lane >> 2, cq = (lane & 3) * 2;
#pragma unroll
    for (int i = 0; i < 4; i++) {
#pragma unroll
        for (int j = 0; j < 8; j++) {
            int row = m0 + mwb + i * 16 + rq;
            int col = n0 + nwb + j * 8 + cq;
            *(float2*)&C[(size_t)row * ldc + col] = make_float2(acc[i][j][0], acc[i][j][1]);
            *(float2*)&C[(size_t)(row + 8) * ldc + col] = make_float2(acc[i][j][2], acc[i][j][3]);
        }
    }
}

// ---------------------------------------------------------------------------
// Tensor-core flash attention (R13 proven version): single-buffered K/V.
// BQ=64, BK=64, 128 threads.
// smem: Q 64x136h (17408B), K 64x136h (17408B), V 128x72h (18432B) = 53248 B.
// ---------------------------------------------------------------------------
#define AT_QH 0
#define AT_KH 17408
#define AT_VH 34816
#define AT_SMEM 53248

__global__ __launch_bounds__(128) void attn_tc(__half* __restrict__ ahi)
{
    extern __shared__ __align__(16) char sm[];
    const uint32_t sb = smem_u32(sm);
    const int tid = threadIdx.x, warp = tid >> 5, lane = tid & 31;
    const int h = blockIdx.y, q0 = blockIdx.x * 64, kvh = h >> 2;

    const __half* qg = g_qh + ((size_t)h * SEQ + q0) * DHEAD;
    const __half* kg = g_kh + (size_t)kvh * SEQ * DHEAD;
    const __half* vg = g_vt + (size_t)kvh * DHEAD * SEQ;

    // Q tile load (once)
#pragma unroll
    for (int i = 0; i < 8; i++) {
        int op = tid + 128 * i;
        int row = op >> 4, ch = op & 15;
        CP_ASYNC16(sb + AT_QH + row * 272 + ch * 16, qg + row * DHEAD + ch * 8);
    }
    CP_COMMIT();

    float m0 = -1e30f, m1 = -1e30f, l0 = 0.f, l1 = 0.f;
    float o[16][4];
#pragma unroll
    for (int j = 0; j < 16; j++)
#pragma unroll
        for (int e = 0; e < 4; e++) o[j][e] = 0.f;

    int jlo = q0 - (WIN - 1); if (jlo < 0) jlo = 0;
    int t0 = jlo & ~63;
    int ntiles = (q0 + 64 - t0) >> 6;

    const int rq = lane >> 2;
    const int qi0 = q0 + 16 * warp + rq, qi1 = qi0 + 8;

    for (int t = 0; t < ntiles; t++) {
        const int jb = t0 + t * 64;
#pragma unroll
        for (int i = 0; i < 8; i++) {
            int op = tid + 128 * i;
            int row = op >> 4, ch = op & 15;
            CP_ASYNC16(sb + AT_KH + row * 272 + ch * 16,
                       kg + (size_t)(jb + row) * DHEAD + ch * 8);
        }
#pragma unroll
        for (int i = 0; i < 8; i++) {
            int op = tid + 128 * i;
            int row = op >> 3, ch = op & 7;
            CP_ASYNC16(sb + AT_VH + row * 144 + ch * 16,
                       vg + (size_t)row * SEQ + jb + ch * 8);
        }
        CP_COMMIT();
        CP_WAIT(0);
        __syncthreads();

        // scores: S = Q @ K^T
        float sacc[8][4];
#pragma unroll
        for (int j = 0; j < 8; j++)
#pragma unroll
            for (int e = 0; e < 4; e++) sacc[j][e] = 0.f;
#pragma unroll
        for (int kc = 0; kc < 8; kc++) {
            uint32_t qf[4];
            uint32_t qa = sb + AT_QH + (16 * warp + (lane & 15)) * 272 +
                          (2 * kc + (lane >> 4)) * 16;
            ldsm_x4(qf, qa);
#pragma unroll
            for (int j = 0; j < 8; j++) {
                uint32_t kf[2];
                uint32_t ka = sb + AT_KH + (8 * j + (lane & 7)) * 272 +
                              (2 * kc + ((lane >> 3) & 1)) * 16;
                ldsm_x2(kf, ka);
                mma_f16(sacc[j], qf, kf);
            }
        }

        // mask + running max
        float mt0 = -1e30f, mt1 = -1e30f;
#pragma unroll
        for (int j = 0; j < 8; j++) {
            int kj = jb + 8 * j + 2 * (lane & 3);
            if (!((kj     <= qi0) && (qi0 - kj     < WIN))) sacc[j][0] = -1e30f;
            if (!((kj + 1 <= qi0) && (qi0 - kj - 1 < WIN))) sacc[j][1] = -1e30f;
            if (!((kj     <= qi1) && (qi1 - kj     < WIN))) sacc[j][2] = -1e30f;
            if (!((kj + 1 <= qi1) && (qi1 - kj - 1 < WIN))) sacc[j][3] = -1e30f;
            mt0 = fmaxf(mt0, fmaxf(sacc[j][0], sacc[j][1]));
            mt1 = fmaxf(mt1, fmaxf(sacc[j][2], sacc[j][3]));
        }
        mt0 = fmaxf(mt0, __shfl_xor_sync(0xffffffffu, mt0, 1));
        mt0 = fmaxf(mt0, __shfl_xor_sync(0xffffffffu, mt0, 2));
        mt1 = fmaxf(mt1, __shfl_xor_sync(0xffffffffu, mt1, 1));
        mt1 = fmaxf(mt1, __shfl_xor_sync(0xffffffffu, mt1, 2));
        float mn0 = fmaxf(m0, mt0), mn1 = fmaxf(m1, mt1);
        float f0 = exp2f(m0 - mn0), f1 = exp2f(m1 - mn1);
        m0 = mn0; m1 = mn1;

        // exp (base-2) + row sums
        float rs0 = 0.f, rs1 = 0.f;
#pragma unroll
        for (int j = 0; j < 8; j++) {
            sacc[j][0] = (sacc[j][0] > -1e29f) ? exp2f(sacc[j][0] - mn0) : 0.f;
            sacc[j][1] = (sacc[j][1] > -1e29f) ? exp2f(sacc[j][1] - mn0) : 0.f;
            sacc[j][2] = (sacc[j][2] > -1e29f) ? exp2f(sacc[j][2] - mn1) : 0.f;
            sacc[j][3] = (sacc[j][3] > -1e29f) ? exp2f(sacc[j][3] - mn1) : 0.f;
            rs0 += sacc[j][0] + sacc[j][1];
            rs1 += sacc[j][2] + sacc[j][3];
        }
        rs0 += __shfl_xor_sync(0xffffffffu, rs0, 1);
        rs0 += __shfl_xor_sync(0xffffffffu, rs0, 2);
        rs1 += __shfl_xor_sync(0xffffffffu, rs1, 1);
        rs1 += __shfl_xor_sync(0xffffffffu, rs1, 2);
        l0 = l0 * f0 + rs0;
        l1 = l1 * f1 + rs1;

        // rescale O
#pragma unroll
        for (int j = 0; j < 16; j++) {
            o[j][0] *= f0; o[j][1] *= f0;
            o[j][2] *= f1; o[j][3] *= f1;
        }

        // pack P into fp16 A-frags (reg->reg)
        uint32_t pa[4][4];
#pragma unroll
        for (int kch = 0; kch < 4; kch++) {
#pragma unroll
            for (int e = 0; e < 4; e++) {
                int jj = 2 * kch + (e >> 1);
                int b = (e & 1) * 2;
                __half2 ph = __float22half2_rn(make_float2(sacc[jj][b], sacc[jj][b + 1]));
                pa[kch][e] = *(uint32_t*)&ph;
            }
        }

        // O += P @ V
#pragma unroll
        for (int kch = 0; kch < 4; kch++) {
#pragma unroll
            for (int j = 0; j < 16; j++) {
                uint32_t vf[2];
                uint32_t va = sb + AT_VH + (8 * j + (lane & 7)) * 144 +
                              (2 * kch + ((lane >> 3) & 1)) * 16;
                ldsm_x2(vf, va);
                mma_f16(o[j], pa[kch], vf);
            }
        }
        __syncthreads();
    }

    // epilogue: normalize, store fp16 [s][h*128+d]
    float inv0 = 1.f / l0, inv1 = 1.f / l1;
    size_t r0b = (size_t)qi0 * DMODEL + h * DHEAD;
    size_t r1b = (size_t)qi1 * DMODEL + h * DHEAD;
#pragma unroll
    for (int j = 0; j < 16; j++) {
        int d = 8 * j + 2 * (lane & 3);
        __half2 h0 = __float22half2_rn(make_float2(o[j][0] * inv0, o[j][1] * inv0));
        __half2 h1 = __float22half2_rn(make_float2(o[j][2] * inv1, o[j][3] * inv1));
        *(uint32_t*)&ahi[r0b + d] = *(uint32_t*)&h0;
        *(uint32_t*)&ahi[r1b + d] = *(uint32_t*)&h1;
    }
}

// ---------------------------------------------------------------------------
extern "C" void kernel_launch(void* const* d_in, const int* in_sizes, int n_in,
                              void* d_out, int out_size)
{
    const float* x    = (const float*)d_in[0];
    const float* cosc = (const float*)d_in[1];
    const float* sinc = (const float*)d_in[2];
    // d_in[3] positions (== arange), d_in[4] attn_mask: handled analytically
    const float* Wq = (const float*)d_in[5];
    const float* Wk = (const float*)d_in[6];
    const float* Wv = (const float*)d_in[7];
    const float* Wo = (const float*)d_in[8];
    float* out = (float*)d_out;

    __half *xh, *wt, *wo, *ah;
    cudaGetSymbolAddress((void**)&xh, g_xh);
    cudaGetSymbolAddress((void**)&wt, g_wt);
    cudaGetSymbolAddress((void**)&wo, g_wo);
    cudaGetSymbolAddress((void**)&ah, g_a_hi);

    // 1. convert x to fp16; transpose all weights (one launch)
    econv<<<4096, 256>>>((const float4*)x, xh, SEQ * DMODEL / 4);
    ttrans_all<<<dim3(160, 64), dim3(32, 8)>>>(Wq, Wk, Wv, Wo, wt, wo);

    cudaFuncSetAttribute(gemm_qkv, cudaFuncAttributeMaxDynamicSharedMemorySize, GS1_SMEM);
    cudaFuncSetAttribute(gemm_mma1, cudaFuncAttributeMaxDynamicSharedMemorySize, GS1_SMEM);
    cudaFuncSetAttribute(attn_tc, cudaFuncAttributeMaxDynamicSharedMemorySize, AT_SMEM);

    // 2. Fused QKV projection + RoPE + scatter (64x64 warp tiles)
    gemm_qkv<<<dim3(24, 16), 128, GS1_SMEM>>>(xh, wt, cosc, sinc, out);

    // 3. Tensor-core attention (R13 proven version)
    attn_tc<<<dim3(SEQ / 64, NHQ), 128, AT_SMEM>>>(ah);

    // 4. Output projection (64x64 warp tiles)
    gemm_mma1<<<dim3(16, 16), 128, GS1_SMEM>>>(ah, wo, out, DMODEL);
}

// round 16
// speedup vs baseline: 1.0731x; 1.0731x over previous
#include <cuda_runtime.h>
#include <cuda_bf16.h>
#include <cuda_fp16.h>
#include <cstdint>

#define SEQ 2048
#define DMODEL 2048
#define NHQ 16
#define NHKV 4
#define DHEAD 128
#define WIN 512

#define QKV_COLS 3072
#define K_OFF 4194304   // 2048*2048
#define V_OFF 5242880   // + 4*2048*128

#define QSCALE (0.08838834764831845f * 1.4426950408889634f)  // 1/sqrt(128) * log2(e)

// ---------------------------------------------------------------------------
// Scratch (device globals; 16B-aligned)
// ---------------------------------------------------------------------------
__device__ __align__(16) __half g_xh[SEQ * DMODEL];         // x in fp16
__device__ __align__(16) __half g_wt[QKV_COLS * DMODEL];    // [Wq^T;Wk^T;Wv^T], fp16
__device__ __align__(16) __half g_wo[DMODEL * DMODEL];      // Wo^T, fp16
__device__ __align__(16) __half g_a_hi[SEQ * DMODEL];       // attention output (fp16)
// attention operands (fp16)
__device__ __align__(16) __half g_qh[NHQ * SEQ * DHEAD];    // [h][s][d], scaled
__device__ __align__(16) __half g_kh[NHKV * SEQ * DHEAD];   // [kvh][s][d]
__device__ __align__(16) __half g_vt[NHKV * DHEAD * SEQ];   // [kvh][d][s]

// ---------------------------------------------------------------------------
// mma.sync helpers (baseline sm_80+ PTX)
// ---------------------------------------------------------------------------
__device__ __forceinline__ uint32_t smem_u32(const void* p) {
    uint32_t a;
    asm("{ .reg .u64 t; cvta.to.shared.u64 t, %1; cvt.u32.u64 %0, t; }" : "=r"(a) : "l"(p));
    return a;
}
__device__ __forceinline__ void ldsm_x4(uint32_t* r, uint32_t a) {
    asm volatile("ldmatrix.sync.aligned.m8n8.x4.shared.b16 {%0,%1,%2,%3}, [%4];"
                 : "=r"(r[0]), "=r"(r[1]), "=r"(r[2]), "=r"(r[3]) : "r"(a));
}
__device__ __forceinline__ void ldsm_x2(uint32_t* r, uint32_t a) {
    asm volatile("ldmatrix.sync.aligned.m8n8.x2.shared.b16 {%0,%1}, [%2];"
                 : "=r"(r[0]), "=r"(r[1]) : "r"(a));
}
__device__ __forceinline__ void mma_f16(float* c, const uint32_t* a, const uint32_t* b) {
    asm volatile(
        "mma.sync.aligned.m16n8k16.row.col.f32.f16.f16.f32 "
        "{%0,%1,%2,%3}, {%4,%5,%6,%7}, {%8,%9}, {%0,%1,%2,%3};"
        : "+f"(c[0]), "+f"(c[1]), "+f"(c[2]), "+f"(c[3])
        : "r"(a[0]), "r"(a[1]), "r"(a[2]), "r"(a[3]), "r"(b[0]), "r"(b[1]));
}
#define CP_ASYNC16(s, g) \
    asm volatile("cp.async.cg.shared.global [%0], [%1], 16;" :: "r"(s), "l"(g))
#define CP_COMMIT() asm volatile("cp.async.commit_group;" ::: "memory")
#define CP_WAIT(n)  asm volatile("cp.async.wait_group %0;" :: "n"(n) : "memory")

// ---------------------------------------------------------------------------
// fp32 -> fp16 convert (elementwise)
// ---------------------------------------------------------------------------
__global__ __launch_bounds__(256) void econv(
    const float4* __restrict__ A, __half* __restrict__ out, int n4)
{
    int i = blockIdx.x * 256 + threadIdx.x;
    if (i >= n4) return;
    float4 v = A[i];
    __half2 a = __float22half2_rn(make_float2(v.x, v.y));
    __half2 b = __float22half2_rn(make_float2(v.z, v.w));
    *(uint32_t*)&out[4 * i]     = *(uint32_t*)&a;
    *(uint32_t*)&out[4 * i + 2] = *(uint32_t*)&b;
}

// ---------------------------------------------------------------------------
// Batched transpose to fp16: all four weights in one launch.
// ---------------------------------------------------------------------------
__global__ __launch_bounds__(256) void ttrans_all(
    const float* __restrict__ Wq, const float* __restrict__ Wk,
    const float* __restrict__ Wv, const float* __restrict__ Wo,
    __half* __restrict__ wt, __half* __restrict__ wo)
{
    __shared__ float t[32][33];
    int tx = threadIdx.x, ty = threadIdx.y;
    int bx = blockIdx.x;

    const float* W; __half* T; int N; int nb;
    if (bx < 64)       { W = Wq; T = wt;               N = 2048; nb = bx; }
    else if (bx < 80)  { W = Wk; T = wt + 2048 * 2048; N = 512;  nb = bx - 64; }
    else if (bx < 96)  { W = Wv; T = wt + 2560 * 2048; N = 512;  nb = bx - 80; }
    else               { W = Wo; T = wo;               N = 2048; nb = bx - 96; }

    int n0 = nb * 32, k0 = blockIdx.y * 32;
#pragma unroll
    for (int i = 0; i < 4; i++)
        t[ty + 8 * i][tx] = W[(size_t)(k0 + ty + 8 * i) * N + n0 + tx];
    __syncthreads();
#pragma unroll
    for (int i = 0; i < 4; i++)
        T[(size_t)(n0 + ty + 8 * i) * 2048 + k0 + tx] = __float2half(t[tx][ty + 8 * i]);
}

// ---------------------------------------------------------------------------
// GEMM mainloop (R13 proven): CTA 128x128, 256 threads, 8 warps (2m x 4n),
// warp tile 64x32. KC=64, row stride 72 halves, 2-stage cp.async pipeline.
// ---------------------------------------------------------------------------
#define KC 64
#define NCHUNK (2048 / KC)
#define TILE_B 18432          // 128 rows * 72 halves * 2B
#define STAGE1_B (2 * TILE_B)
#define GS1_SMEM (2 * STAGE1_B)   // 73728 B (>= 128*130*4 = 66560 epilogue tile)

#define GEMM_MAINLOOP(Aptr, Bptr)                                              \
    float acc[4][4][4];                                                        \
    _Pragma("unroll")                                                          \
    for (int i = 0; i < 4; i++)                                                \
        _Pragma("unroll")                                                      \
        for (int j = 0; j < 4; j++)                                            \
            _Pragma("unroll")                                                  \
            for (int e = 0; e < 4; e++) acc[i][j][e] = 0.f;                    \
    auto load_chunk = [&](int c, int buf) {                                    \
        const int k0 = c * KC;                                                 \
        const uint32_t st = sbase + buf * STAGE1_B;                            \
        _Pragma("unroll")                                                      \
        for (int i = 0; i < 4; i++) {                                          \
            int op = t + 256 * i;                                              \
            int r = op >> 3, ch = op & 7;                                      \
            uint32_t so = (uint32_t)(r * 144 + ch * 16);                       \
            const size_t go = (size_t)r * 2048 + k0 + ch * 8;                  \
            CP_ASYNC16(st + so, (Aptr) + (size_t)m0 * 2048 + go);              \
            CP_ASYNC16(st + TILE_B + so, (Bptr) + (size_t)n0 * 2048 + go);     \
        }                                                                      \
    };                                                                         \
    load_chunk(0, 0);                                                          \
    CP_COMMIT();                                                               \
    for (int c = 0; c < NCHUNK; c++) {                                         \
        const int buf = c & 1;                                                 \
        if (c + 1 < NCHUNK) { load_chunk(c + 1, (c + 1) & 1); CP_COMMIT(); CP_WAIT(1); } \
        else { CP_WAIT(0); }                                                   \
        __syncthreads();                                                       \
        const uint32_t sA = sbase + buf * STAGE1_B;                            \
        const uint32_t sB = sA + TILE_B;                                       \
        const int arow = mwb + (lane & 15);                                    \
        const int brow = nwb + (lane & 7);                                     \
        _Pragma("unroll")                                                      \
        for (int ks = 0; ks < 4; ks++) {                                       \
            const int kc = ks * 2;                                             \
            uint32_t af[4][4], bf[4][2];                                       \
            const int ach = kc + (lane >> 4);                                  \
            const int bch = kc + ((lane >> 3) & 1);                            \
            _Pragma("unroll")                                                  \
            for (int i = 0; i < 4; i++)                                        \
                ldsm_x4(af[i], sA + (uint32_t)((arow + i * 16) * 144 + ach * 16)); \
            _Pragma("unroll")                                                  \
            for (int j = 0; j < 4; j++)                                        \
                ldsm_x2(bf[j], sB + (uint32_t)((brow + j * 8) * 144 + bch * 16)); \
            _Pragma("unroll")                                                  \
            for (int i = 0; i < 4; i++)                                        \
                _Pragma("unroll")                                              \
                for (int j = 0; j < 4; j++)                                    \
                    mma_f16(acc[i][j], af[i], bf[j]);                          \
        }                                                                      \
        __syncthreads();                                                       \
    }

// ---------------------------------------------------------------------------
// QKV GEMM with fused RoPE + scatter epilogue. Grid (24, 16), 256 threads.
// ---------------------------------------------------------------------------
__global__ __launch_bounds__(256, 2) void gemm_qkv(
    const __half* __restrict__ A, const __half* __restrict__ Bw,
    const float* __restrict__ cosc, const float* __restrict__ sinc,
    float* __restrict__ out)
{
    extern __shared__ __align__(16) char sm[];
    const uint32_t sbase = smem_u32(sm);
    const int t = threadIdx.x;
    const int warp = t >> 5, lane = t & 31;
    const int mwb = (warp & 1) * 64;
    const int nwb = (warp >> 1) * 32;
    const int m0 = blockIdx.y * 128, n0 = blockIdx.x * 128;

    GEMM_MAINLOOP(A, Bw)

    // stage fp32 tile in smem, stride 130 floats
    float* ts = (float*)sm;
    const int rq = lane >> 2, cq = (lane & 3) * 2;
#pragma unroll
    for (int i = 0; i < 4; i++) {
#pragma unroll
        for (int j = 0; j < 4; j++) {
            int row = mwb + i * 16 + rq;
            int col = nwb + j * 8 + cq;
            *(float2*)&ts[row * 130 + col] = make_float2(acc[i][j][0], acc[i][j][1]);
            *(float2*)&ts[(row + 8) * 130 + col] = make_float2(acc[i][j][2], acc[i][j][3]);
        }
    }
    __syncthreads();

    if (n0 < 2048) {
        const int h = n0 >> 7;
        for (int e = t; e < 128 * 128; e += 256) {
            int r = e >> 7, d = e & 127;
            int s = m0 + r;
            float v = ts[r * 130 + d];
            float pr = ts[r * 130 + (d ^ 64)];
            float rot = (d < 64) ? -pr : pr;
            float q = (v * cosc[s * DHEAD + d] + rot * sinc[s * DHEAD + d]) * QSCALE;
            g_qh[((size_t)h * SEQ + s) * DHEAD + d] = __float2half(q);
        }
    } else if (n0 < 2560) {
        const int kvh = (n0 - 2048) >> 7;
        for (int e = t; e < 128 * 128; e += 256) {
            int r = e >> 7, d = e & 127;
            int s = m0 + r;
            float v = ts[r * 130 + d];
            float pr = ts[r * 130 + (d ^ 64)];
            float rot = (d < 64) ? -pr : pr;
            float rv = v * cosc[s * DHEAD + d] + rot * sinc[s * DHEAD + d];
            size_t o = ((size_t)kvh * SEQ + s) * DHEAD + d;
            out[K_OFF + o] = rv;
            g_kh[o] = __float2half(rv);
        }
    } else {
        const int kvh = (n0 - 2560) >> 7;
        for (int e = t; e < 128 * 128; e += 256) {
            int r = e >> 7, d = e & 127;
            out[V_OFF + ((size_t)kvh * SEQ + m0 + r) * DHEAD + d] = ts[r * 130 + d];
        }
        for (int e = t; e < 128 * 128; e += 256) {
            int d = e >> 7, sl = e & 127;
            g_vt[((size_t)kvh * DHEAD + d) * SEQ + m0 + sl] =
                __float2half(ts[sl * 130 + d]);
        }
    }
}

// ---------------------------------------------------------------------------
// Plain single-pass fp16 GEMM (Wo projection), 256 threads, 2 CTAs/SM.
// ---------------------------------------------------------------------------
__global__ __launch_bounds__(256, 2) void gemm_mma1(
    const __half* __restrict__ A, const __half* __restrict__ B,
    float* __restrict__ C, int ldc)
{
    extern __shared__ __align__(16) char sm[];
    const uint32_t sbase = smem_u32(sm);
    const int t = threadIdx.x;
    const int warp = t >> 5, lane = t & 31;
    const int mwb = (warp & 1) * 64;
    const int nwb = (warp >> 1) * 32;
    const int m0 = blockIdx.y * 128, n0 = blockIdx.x * 128;

    GEMM_MAINLOOP(A, B)

    const int rq = lane >> 2, cq = (lane & 3) * 2;
#pragma unroll
    for (int i = 0; i < 4; i++) {
#pragma unroll
        for (int j = 0; j < 4; j++) {
            int row = m0 + mwb + i * 16 + rq;
            int col = n0 + nwb + j * 8 + cq;
            *(float2*)&C[(size_t)row * ldc + col] = make_float2(acc[i][j][0], acc[i][j][1]);
            *(float2*)&C[(size_t)(row + 8) * ldc + col] = make_float2(acc[i][j][2], acc[i][j][3]);
        }
    }
}

// ---------------------------------------------------------------------------
// Tensor-core flash attention with split-group K/V overlap.
// K(t+1) issued after S(t) (K buffer dead), overlapping softmax+PV(t).
// V(t+1) issued after PV(t) (V buffer dead), overlapping S(t+1)+softmax(t+1).
// Same smem as R13: Q 17408 + K 17408 + V 18432 = 53248 B, 3 CTAs/SM.
// ---------------------------------------------------------------------------
#define AT_QH 0
#define AT_KH 17408
#define AT_VH 34816
#define AT_SMEM 53248

__global__ __launch_bounds__(128) void attn_tc(__half* __restrict__ ahi)
{
    extern __shared__ __align__(16) char sm[];
    const uint32_t sb = smem_u32(sm);
    const int tid = threadIdx.x, warp = tid >> 5, lane = tid & 31;
    const int h = blockIdx.y, q0 = blockIdx.x * 64, kvh = h >> 2;

    const __half* qg = g_qh + ((size_t)h * SEQ + q0) * DHEAD;
    const __half* kg = g_kh + (size_t)kvh * SEQ * DHEAD;
    const __half* vg = g_vt + (size_t)kvh * DHEAD * SEQ;

    int jlo = q0 - (WIN - 1); if (jlo < 0) jlo = 0;
    int t0 = jlo & ~63;
    int ntiles = (q0 + 64 - t0) >> 6;

    auto load_k = [&](int tile) {
        const int jb = t0 + tile * 64;
#pragma unroll
        for (int i = 0; i < 8; i++) {
            int op = tid + 128 * i;
            int row = op >> 4, ch = op & 15;
            CP_ASYNC16(sb + AT_KH + row * 272 + ch * 16,
                       kg + (size_t)(jb + row) * DHEAD + ch * 8);
        }
    };
    auto load_v = [&](int tile) {
        const int jb = t0 + tile * 64;
#pragma unroll
        for (int i = 0; i < 8; i++) {
            int op = tid + 128 * i;
            int row = op >> 3, ch = op & 7;
            CP_ASYNC16(sb + AT_VH + row * 144 + ch * 16,
                       vg + (size_t)row * SEQ + jb + ch * 8);
        }
    };

    // prologue: Q | K0 | V0 as separate commit groups
#pragma unroll
    for (int i = 0; i < 8; i++) {
        int op = tid + 128 * i;
        int row = op >> 4, ch = op & 15;
        CP_ASYNC16(sb + AT_QH + row * 272 + ch * 16, qg + row * DHEAD + ch * 8);
    }
    CP_COMMIT();
    load_k(0); CP_COMMIT();
    load_v(0); CP_COMMIT();

    float m0 = -1e30f, m1 = -1e30f, l0 = 0.f, l1 = 0.f;
    float o[16][4];
#pragma unroll
    for (int j = 0; j < 16; j++)
#pragma unroll
        for (int e = 0; e < 4; e++) o[j][e] = 0.f;

    const int rq = lane >> 2;
    const int qi0 = q0 + 16 * warp + rq, qi1 = qi0 + 8;

    for (int t = 0; t < ntiles; t++) {
        const int jb = t0 + t * 64;
        const bool more = (t + 1 < ntiles);

        // wait for Q (t==0) and K(t); V(t) may still be in flight
        CP_WAIT(1);
        __syncthreads();

        // scores: S = Q @ K^T
        float sacc[8][4];
#pragma unroll
        for (int j = 0; j < 8; j++)
#pragma unroll
            for (int e = 0; e < 4; e++) sacc[j][e] = 0.f;
#pragma unroll
        for (int kc = 0; kc < 8; kc++) {
            uint32_t qf[4];
            uint32_t qa = sb + AT_QH + (16 * warp + (lane & 15)) * 272 +
                          (2 * kc + (lane >> 4)) * 16;
            ldsm_x4(qf, qa);
#pragma unroll
            for (int j = 0; j < 8; j++) {
                uint32_t kf[2];
                uint32_t ka = sb + AT_KH + (8 * j + (lane & 7)) * 272 +
                              (2 * kc + ((lane >> 3) & 1)) * 16;
                ldsm_x2(kf, ka);
                mma_f16(sacc[j], qf, kf);
            }
        }
        __syncthreads();              // all warps done reading K buffer
        if (more) { load_k(t + 1); CP_COMMIT(); }   // overlap with softmax+PV

        // mask + running max
        float mt0 = -1e30f, mt1 = -1e30f;
#pragma unroll
        for (int j = 0; j < 8; j++) {
            int kj = jb + 8 * j + 2 * (lane & 3);
            if (!((kj     <= qi0) && (qi0 - kj     < WIN))) sacc[j][0] = -1e30f;
            if (!((kj + 1 <= qi0) && (qi0 - kj - 1 < WIN))) sacc[j][1] = -1e30f;
            if (!((kj     <= qi1) && (qi1 - kj     < WIN))) sacc[j][2] = -1e30f;
            if (!((kj + 1 <= qi1) && (qi1 - kj - 1 < WIN))) sacc[j][3] = -1e30f;
            mt0 = fmaxf(mt0, fmaxf(sacc[j][0], sacc[j][1]));
            mt1 = fmaxf(mt1, fmaxf(sacc[j][2], sacc[j][3]));
        }
        mt0 = fmaxf(mt0, __shfl_xor_sync(0xffffffffu, mt0, 1));
        mt0 = fmaxf(mt0, __shfl_xor_sync(0xffffffffu, mt0, 2));
        mt1 = fmaxf(mt1, __shfl_xor_sync(0xffffffffu, mt1, 1));
        mt1 = fmaxf(mt1, __shfl_xor_sync(0xffffffffu, mt1, 2));
        float mn0 = fmaxf(m0, mt0), mn1 = fmaxf(m1, mt1);
        float f0 = exp2f(m0 - mn0), f1 = exp2f(m1 - mn1);
        m0 = mn0; m1 = mn1;

        // exp (base-2) + row sums
        float rs0 = 0.f, rs1 = 0.f;
#pragma unroll
        for (int j = 0; j < 8; j++) {
            sacc[j][0] = (sacc[j][0] > -1e29f) ? exp2f(sacc[j][0] - mn0) : 0.f;
            sacc[j][1] = (sacc[j][1] > -1e29f) ? exp2f(sacc[j][1] - mn0) : 0.f;
            sacc[j][2] = (sacc[j][2] > -1e29f) ? exp2f(sacc[j][2] - mn1) : 0.f;
            sacc[j][3] = (sacc[j][3] > -1e29f) ? exp2f(sacc[j][3] - mn1) : 0.f;
            rs0 += sacc[j][0] + sacc[j][1];
            rs1 += sacc[j][2] + sacc[j][3];
        }
        rs0 += __shfl_xor_sync(0xffffffffu, rs0, 1);
        rs0 += __shfl_xor_sync(0xffffffffu, rs0, 2);
        rs1 += __shfl_xor_sync(0xffffffffu, rs1, 1);
        rs1 += __shfl_xor_sync(0xffffffffu, rs1, 2);
        l0 = l0 * f0 + rs0;
        l1 = l1 * f1 + rs1;

        // rescale O
#pragma unroll
        for (int j = 0; j < 16; j++) {
            o[j][0] *= f0; o[j][1] *= f0;
            o[j][2] *= f1; o[j][3] *= f1;
        }

        // pack P into fp16 A-frags (reg->reg)
        uint32_t pa[4][4];
#pragma unroll
        for (int kch = 0; kch < 4; kch++) {
#pragma unroll
            for (int e = 0; e < 4; e++) {
                int jj = 2 * kch + (e >> 1);
                int b = (e & 1) * 2;
                __half2 ph = __float22half2_rn(make_float2(sacc[jj][b], sacc[jj][b + 1]));
                pa[kch][e] = *(uint32_t*)&ph;
            }
        }

        // wait for V(t): K(t+1) (if issued) remains in flight
        if (more) CP_WAIT(1); else CP_WAIT(0);
        __syncthreads();

        // O += P @ V
#pragma unroll
        for (int kch = 0; kch < 4; kch++) {
#pragma unroll
            for (int j = 0; j < 16; j++) {
                uint32_t vf[2];
                uint32_t va = sb + AT_VH + (8 * j + (lane & 7)) * 144 +
                              (2 * kch + ((lane >> 3) & 1)) * 16;
                ldsm_x2(vf, va);
                mma_f16(o[j], pa[kch], vf);
            }
        }
        __syncthreads();              // all warps done reading V buffer
        if (more) { load_v(t + 1); CP_COMMIT(); }   // overlap with next S
    }

    // epilogue: normalize, store fp16 [s][h*128+d]
    float inv0 = 1.f / l0, inv1 = 1.f / l1;
    size_t r0b = (size_t)qi0 * DMODEL + h * DHEAD;
    size_t r1b = (size_t)qi1 * DMODEL + h * DHEAD;
#pragma unroll
    for (int j = 0; j < 16; j++) {
        int d = 8 * j + 2 * (lane & 3);
        __half2 h0 = __float22half2_rn(make_float2(o[j][0] * inv0, o[j][1] * inv0));
        __half2 h1 = __float22half2_rn(make_float2(o[j][2] * inv1, o[j][3] * inv1));
        *(uint32_t*)&ahi[r0b + d] = *(uint32_t*)&h0;
        *(uint32_t*)&ahi[r1b + d] = *(uint32_t*)&h1;
    }
}

// ---------------------------------------------------------------------------
extern "C" void kernel_launch(void* const* d_in, const int* in_sizes, int n_in,
                              void* d_out, int out_size)
{
    const float* x    = (const float*)d_in[0];
    const float* cosc = (const float*)d_in[1];
    const float* sinc = (const float*)d_in[2];
    // d_in[3] positions (== arange), d_in[4] attn_mask: handled analytically
    const float* Wq = (const float*)d_in[5];
    const float* Wk = (const float*)d_in[6];
    const float* Wv = (const float*)d_in[7];
    const float* Wo = (const float*)d_in[8];
    float* out = (float*)d_out;

    __half *xh, *wt, *wo, *ah;
    cudaGetSymbolAddress((void**)&xh, g_xh);
    cudaGetSymbolAddress((void**)&wt, g_wt);
    cudaGetSymbolAddress((void**)&wo, g_wo);
    cudaGetSymbolAddress((void**)&ah, g_a_hi);

    // 1. convert x to fp16; transpose all weights (one launch)
    econv<<<4096, 256>>>((const float4*)x, xh, SEQ * DMODEL / 4);
    ttrans_all<<<dim3(160, 64), dim3(32, 8)>>>(Wq, Wk, Wv, Wo, wt, wo);

    cudaFuncSetAttribute(gemm_qkv, cudaFuncAttributeMaxDynamicSharedMemorySize, GS1_SMEM);
    cudaFuncSetAttribute(gemm_mma1, cudaFuncAttributeMaxDynamicSharedMemorySize, GS1_SMEM);
    cudaFuncSetAttribute(attn_tc, cudaFuncAttributeMaxDynamicSharedMemorySize, AT_SMEM);

    // 2. Fused QKV projection + RoPE + scatter (R13 GEMM config)
    gemm_qkv<<<dim3(24, 16), 256, GS1_SMEM>>>(xh, wt, cosc, sinc, out);

    // 3. Tensor-core attention (split-group K/V overlap)
    attn_tc<<<dim3(SEQ / 64, NHQ), 128, AT_SMEM>>>(ah);

    // 4. Output projection (R13 GEMM config)
    gemm_mma1<<<dim3(16, 16), 256, GS1_SMEM>>>(ah, wo, out, DMODEL);
}

// round 17
// speedup vs baseline: 1.1113x; 1.0357x over previous
#include <cuda_runtime.h>
#include <cuda_bf16.h>
#include <cuda_fp16.h>
#include <cstdint>

#define SEQ 2048
#define DMODEL 2048
#define NHQ 16
#define NHKV 4
#define DHEAD 128
#define WIN 512

#define QKV_COLS 3072
#define K_OFF 4194304   // 2048*2048
#define V_OFF 5242880   // + 4*2048*128

#define QSCALE (0.08838834764831845f * 1.4426950408889634f)  // 1/sqrt(128) * log2(e)

// ---------------------------------------------------------------------------
// Scratch (device globals; 16B-aligned)
// ---------------------------------------------------------------------------
__device__ __align__(16) __half g_xh[SEQ * DMODEL];         // x in fp16
__device__ __align__(16) __half g_wt[QKV_COLS * DMODEL];    // [Wq^T;Wk^T;Wv^T], fp16
__device__ __align__(16) __half g_wo[DMODEL * DMODEL];      // Wo^T, fp16
__device__ __align__(16) __half g_a_hi[SEQ * DMODEL];       // attention output (fp16)
// attention operands (fp16)
__device__ __align__(16) __half g_qh[NHQ * SEQ * DHEAD];    // [h][s][d], scaled
__device__ __align__(16) __half g_kh[NHKV * SEQ * DHEAD];   // [kvh][s][d]
__device__ __align__(16) __half g_vt[NHKV * DHEAD * SEQ];   // [kvh][d][s]

// ---------------------------------------------------------------------------
// mma.sync helpers (baseline sm_80+ PTX)
// ---------------------------------------------------------------------------
__device__ __forceinline__ uint32_t smem_u32(const void* p) {
    uint32_t a;
    asm("{ .reg .u64 t; cvta.to.shared.u64 t, %1; cvt.u32.u64 %0, t; }" : "=r"(a) : "l"(p));
    return a;
}
__device__ __forceinline__ void ldsm_x4(uint32_t* r, uint32_t a) {
    asm volatile("ldmatrix.sync.aligned.m8n8.x4.shared.b16 {%0,%1,%2,%3}, [%4];"
                 : "=r"(r[0]), "=r"(r[1]), "=r"(r[2]), "=r"(r[3]) : "r"(a));
}
__device__ __forceinline__ void ldsm_x2(uint32_t* r, uint32_t a) {
    asm volatile("ldmatrix.sync.aligned.m8n8.x2.shared.b16 {%0,%1}, [%2];"
                 : "=r"(r[0]), "=r"(r[1]) : "r"(a));
}
__device__ __forceinline__ void mma_f16(float* c, const uint32_t* a, const uint32_t* b) {
    asm volatile(
        "mma.sync.aligned.m16n8k16.row.col.f32.f16.f16.f32 "
        "{%0,%1,%2,%3}, {%4,%5,%6,%7}, {%8,%9}, {%0,%1,%2,%3};"
        : "+f"(c[0]), "+f"(c[1]), "+f"(c[2]), "+f"(c[3])
        : "r"(a[0]), "r"(a[1]), "r"(a[2]), "r"(a[3]), "r"(b[0]), "r"(b[1]));
}
#define CP_ASYNC16(s, g) \
    asm volatile("cp.async.cg.shared.global [%0], [%1], 16;" :: "r"(s), "l"(g))
#define CP_COMMIT() asm volatile("cp.async.commit_group;" ::: "memory")
#define CP_WAIT(n)  asm volatile("cp.async.wait_group %0;" :: "n"(n) : "memory")

// ---------------------------------------------------------------------------
// Merged prep: blocks [0,4096) convert x fp32->fp16; blocks [4096,14336)
// transpose the four weight matrices to fp16 (256 threads each).
// ---------------------------------------------------------------------------
__global__ __launch_bounds__(256) void prep_all(
    const float4* __restrict__ x4, __half* __restrict__ xh,
    const float* __restrict__ Wq, const float* __restrict__ Wk,
    const float* __restrict__ Wv, const float* __restrict__ Wo,
    __half* __restrict__ wt, __half* __restrict__ wo)
{
    __shared__ float tbuf[32][33];
    const int bx = blockIdx.x;
    const int t = threadIdx.x;

    if (bx < 4096) {
        int i = bx * 256 + t;
        float4 v = x4[i];
        __half2 a = __float22half2_rn(make_float2(v.x, v.y));
        __half2 b = __float22half2_rn(make_float2(v.z, v.w));
        *(uint32_t*)&xh[4 * i]     = *(uint32_t*)&a;
        *(uint32_t*)&xh[4 * i + 2] = *(uint32_t*)&b;
        return;
    }

    int bz = bx - 4096;
    int gx = bz % 160, gy = bz / 160;      // original grid (160, 64)
    int tx = t & 31, ty = t >> 5;

    const float* W; __half* T; int N; int nb;
    if (gx < 64)       { W = Wq; T = wt;               N = 2048; nb = gx; }
    else if (gx < 80)  { W = Wk; T = wt + 2048 * 2048; N = 512;  nb = gx - 64; }
    else if (gx < 96)  { W = Wv; T = wt + 2560 * 2048; N = 512;  nb = gx - 80; }
    else               { W = Wo; T = wo;               N = 2048; nb = gx - 96; }

    int n0 = nb * 32, k0 = gy * 32;
#pragma unroll
    for (int i = 0; i < 4; i++)
        tbuf[ty + 8 * i][tx] = W[(size_t)(k0 + ty + 8 * i) * N + n0 + tx];
    __syncthreads();
#pragma unroll
    for (int i = 0; i < 4; i++)
        T[(size_t)(n0 + ty + 8 * i) * 2048 + k0 + tx] = __float2half(tbuf[tx][ty + 8 * i]);
}

// ---------------------------------------------------------------------------
// GEMM mainloop (R13 proven): CTA 128x128, 256 threads, 8 warps (2m x 4n),
// warp tile 64x32. KC=64, row stride 72 halves, 2-stage cp.async pipeline.
// ---------------------------------------------------------------------------
#define KC 64
#define NCHUNK (2048 / KC)
#define TILE_B 18432          // 128 rows * 72 halves * 2B
#define STAGE1_B (2 * TILE_B)
#define GS1_SMEM (2 * STAGE1_B)   // 73728 B (>= 128*130*4 = 66560 epilogue tile)

#define GEMM_MAINLOOP(Aptr, Bptr)                                              \
    float acc[4][4][4];                                                        \
    _Pragma("unroll")                                                          \
    for (int i = 0; i < 4; i++)                                                \
        _Pragma("unroll")                                                      \
        for (int j = 0; j < 4; j++)                                            \
            _Pragma("unroll")                                                  \
            for (int e = 0; e < 4; e++) acc[i][j][e] = 0.f;                    \
    auto load_chunk = [&](int c, int buf) {                                    \
        const int k0 = c * KC;                                                 \
        const uint32_t st = sbase + buf * STAGE1_B;                            \
        _Pragma("unroll")                                                      \
        for (int i = 0; i < 4; i++) {                                          \
            int op = t + 256 * i;                                              \
            int r = op >> 3, ch = op & 7;                                      \
            uint32_t so = (uint32_t)(r * 144 + ch * 16);                       \
            const size_t go = (size_t)r * 2048 + k0 + ch * 8;                  \
            CP_ASYNC16(st + so, (Aptr) + (size_t)m0 * 2048 + go);              \
            CP_ASYNC16(st + TILE_B + so, (Bptr) + (size_t)n0 * 2048 + go);     \
        }                                                                      \
    };                                                                         \
    load_chunk(0, 0);                                                          \
    CP_COMMIT();                                                               \
    for (int c = 0; c < NCHUNK; c++) {                                         \
        const int buf = c & 1;                                                 \
        if (c + 1 < NCHUNK) { load_chunk(c + 1, (c + 1) & 1); CP_COMMIT(); CP_WAIT(1); } \
        else { CP_WAIT(0); }                                                   \
        __syncthreads();                                                       \
        const uint32_t sA = sbase + buf * STAGE1_B;                            \
        const uint32_t sB = sA + TILE_B;                                       \
        const int arow = mwb + (lane & 15);                                    \
        const int brow = nwb + (lane & 7);                                     \
        _Pragma("unroll")                                                      \
        for (int ks = 0; ks < 4; ks++) {                                       \
            const int kc = ks * 2;                                             \
            uint32_t af[4][4], bf[4][2];                                       \
            const int ach = kc + (lane >> 4);                                  \
            const int bch = kc + ((lane >> 3) & 1);                            \
            _Pragma("unroll")                                                  \
            for (int i = 0; i < 4; i++)                                        \
                ldsm_x4(af[i], sA + (uint32_t)((arow + i * 16) * 144 + ach * 16)); \
            _Pragma("unroll")                                                  \
            for (int j = 0; j < 4; j++)                                        \
                ldsm_x2(bf[j], sB + (uint32_t)((brow + j * 8) * 144 + bch * 16)); \
            _Pragma("unroll")                                                  \
            for (int i = 0; i < 4; i++)                                        \
                _Pragma("unroll")                                              \
                for (int j = 0; j < 4; j++)                                    \
                    mma_f16(acc[i][j], af[i], bf[j]);                          \
        }                                                                      \
        __syncthreads();                                                       \
    }

// ---------------------------------------------------------------------------
// QKV GEMM with fused RoPE + scatter epilogue. Grid (24, 16), 256 threads.
// ---------------------------------------------------------------------------
__global__ __launch_bounds__(256, 2) void gemm_qkv(
    const __half* __restrict__ A, const __half* __restrict__ Bw,
    const float* __restrict__ cosc, const float* __restrict__ sinc,
    float* __restrict__ out)
{
    extern __shared__ __align__(16) char sm[];
    const uint32_t sbase = smem_u32(sm);
    const int t = threadIdx.x;
    const int warp = t >> 5, lane = t & 31;
    const int mwb = (warp & 1) * 64;
    const int nwb = (warp >> 1) * 32;
    const int m0 = blockIdx.y * 128, n0 = blockIdx.x * 128;

    GEMM_MAINLOOP(A, Bw)

    // stage fp32 tile in smem, stride 130 floats
    float* ts = (float*)sm;
    const int rq = lane >> 2, cq = (lane & 3) * 2;
#pragma unroll
    for (int i = 0; i < 4; i++) {
#pragma unroll
        for (int j = 0; j < 4; j++) {
            int row = mwb + i * 16 + rq;
            int col = nwb + j * 8 + cq;
            *(float2*)&ts[row * 130 + col] = make_float2(acc[i][j][0], acc[i][j][1]);
            *(float2*)&ts[(row + 8) * 130 + col] = make_float2(acc[i][j][2], acc[i][j][3]);
        }
    }
    __syncthreads();

    if (n0 < 2048) {
        const int h = n0 >> 7;
        for (int e = t; e < 128 * 128; e += 256) {
            int r = e >> 7, d = e & 127;
            int s = m0 + r;
            float v = ts[r * 130 + d];
            float pr = ts[r * 130 + (d ^ 64)];
            float rot = (d < 64) ? -pr : pr;
            float q = (v * cosc[s * DHEAD + d] + rot * sinc[s * DHEAD + d]) * QSCALE;
            g_qh[((size_t)h * SEQ + s) * DHEAD + d] = __float2half(q);
        }
    } else if (n0 < 2560) {
        const int kvh = (n0 - 2048) >> 7;
        for (int e = t; e < 128 * 128; e += 256) {
            int r = e >> 7, d = e & 127;
            int s = m0 + r;
            float v = ts[r * 130 + d];
            float pr = ts[r * 130 + (d ^ 64)];
            float rot = (d < 64) ? -pr : pr;
            float rv = v * cosc[s * DHEAD + d] + rot * sinc[s * DHEAD + d];
            size_t o = ((size_t)kvh * SEQ + s) * DHEAD + d;
            out[K_OFF + o] = rv;
            g_kh[o] = __float2half(rv);
        }
    } else {
        const int kvh = (n0 - 2560) >> 7;
        for (int e = t; e < 128 * 128; e += 256) {
            int r = e >> 7, d = e & 127;
            out[V_OFF + ((size_t)kvh * SEQ + m0 + r) * DHEAD + d] = ts[r * 130 + d];
        }
        for (int e = t; e < 128 * 128; e += 256) {
            int d = e >> 7, sl = e & 127;
            g_vt[((size_t)kvh * DHEAD + d) * SEQ + m0 + sl] =
                __float2half(ts[sl * 130 + d]);
        }
    }
}

// ---------------------------------------------------------------------------
// Plain single-pass fp16 GEMM (Wo projection), 256 threads, 2 CTAs/SM.
// ---------------------------------------------------------------------------
__global__ __launch_bounds__(256, 2) void gemm_mma1(
    const __half* __restrict__ A, const __half* __restrict__ B,
    float* __restrict__ C, int ldc)
{
    extern __shared__ __align__(16) char sm[];
    const uint32_t sbase = smem_u32(sm);
    const int t = threadIdx.x;
    const int warp = t >> 5, lane = t & 31;
    const int mwb = (warp & 1) * 64;
    const int nwb = (warp >> 1) * 32;
    const int m0 = blockIdx.y * 128, n0 = blockIdx.x * 128;

    GEMM_MAINLOOP(A, B)

    const int rq = lane >> 2, cq = (lane & 3) * 2;
#pragma unroll
    for (int i = 0; i < 4; i++) {
#pragma unroll
        for (int j = 0; j < 4; j++) {
            int row = m0 + mwb + i * 16 + rq;
            int col = n0 + nwb + j * 8 + cq;
            *(float2*)&C[(size_t)row * ldc + col] = make_float2(acc[i][j][0], acc[i][j][1]);
            *(float2*)&C[(size_t)(row + 8) * ldc + col] = make_float2(acc[i][j][2], acc[i][j][3]);
        }
    }
}

// ---------------------------------------------------------------------------
// Tensor-core flash attention: split-group K/V overlap + x4 ldsm pairing +
// interior-tile mask skip + guard-free exp2 (all bit-exact vs R16).
// smem: Q 17408 + K 17408 + V 18432 = 53248 B, 3 CTAs/SM.
// ---------------------------------------------------------------------------
#define AT_QH 0
#define AT_KH 17408
#define AT_VH 34816
#define AT_SMEM 53248

__global__ __launch_bounds__(128) void attn_tc(__half* __restrict__ ahi)
{
    extern __shared__ __align__(16) char sm[];
    const uint32_t sb = smem_u32(sm);
    const int tid = threadIdx.x, warp = tid >> 5, lane = tid & 31;
    const int h = blockIdx.y, q0 = blockIdx.x * 64, kvh = h >> 2;

    const __half* qg = g_qh + ((size_t)h * SEQ + q0) * DHEAD;
    const __half* kg = g_kh + (size_t)kvh * SEQ * DHEAD;
    const __half* vg = g_vt + (size_t)kvh * DHEAD * SEQ;

    int jlo = q0 - (WIN - 1); if (jlo < 0) jlo = 0;
    int t0 = jlo & ~63;
    int ntiles = (q0 + 64 - t0) >> 6;

    auto load_k = [&](int tile) {
        const int jb = t0 + tile * 64;
#pragma unroll
        for (int i = 0; i < 8; i++) {
            int op = tid + 128 * i;
            int row = op >> 4, ch = op & 15;
            CP_ASYNC16(sb + AT_KH + row * 272 + ch * 16,
                       kg + (size_t)(jb + row) * DHEAD + ch * 8);
        }
    };
    auto load_v = [&](int tile) {
        const int jb = t0 + tile * 64;
#pragma unroll
        for (int i = 0; i < 8; i++) {
            int op = tid + 128 * i;
            int row = op >> 3, ch = op & 7;
            CP_ASYNC16(sb + AT_VH + row * 144 + ch * 16,
                       vg + (size_t)row * SEQ + jb + ch * 8);
        }
    };

    // prologue: Q | K0 | V0 as separate commit groups
#pragma unroll
    for (int i = 0; i < 8; i++) {
        int op = tid + 128 * i;
        int row = op >> 4, ch = op & 15;
        CP_ASYNC16(sb + AT_QH + row * 272 + ch * 16, qg + row * DHEAD + ch * 8);
    }
    CP_COMMIT();
    load_k(0); CP_COMMIT();
    load_v(0); CP_COMMIT();

    float m0 = -1e30f, m1 = -1e30f, l0 = 0.f, l1 = 0.f;
    float o[16][4];
#pragma unroll
    for (int j = 0; j < 16; j++)
#pragma unroll
        for (int e = 0; e < 4; e++) o[j][e] = 0.f;

    const int rq = lane >> 2;
    const int qi0 = q0 + 16 * warp + rq, qi1 = qi0 + 8;
    const int prow = 8 * ((lane >> 4) & 1) + (lane & 7);   // x4 pairing row
    const int phalf = (lane >> 3) & 1;

    for (int t = 0; t < ntiles; t++) {
        const int jb = t0 + t * 64;
        const bool more = (t + 1 < ntiles);

        // wait for Q (t==0) and K(t); V(t) may still be in flight
        CP_WAIT(1);
        __syncthreads();

        // scores: S = Q @ K^T  (K via paired ldsm_x4)
        float sacc[8][4];
#pragma unroll
        for (int j = 0; j < 8; j++)
#pragma unroll
            for (int e = 0; e < 4; e++) sacc[j][e] = 0.f;
#pragma unroll
        for (int kc = 0; kc < 8; kc++) {
            uint32_t qf[4];
            uint32_t qa = sb + AT_QH + (16 * warp + (lane & 15)) * 272 +
                          (2 * kc + (lane >> 4)) * 16;
            ldsm_x4(qf, qa);
#pragma unroll
            for (int jp = 0; jp < 4; jp++) {
                uint32_t kf4[4];
                uint32_t ka = sb + AT_KH + (16 * jp + prow) * 272 +
                              (2 * kc + phalf) * 16;
                ldsm_x4(kf4, ka);
                mma_f16(sacc[2 * jp],     qf, &kf4[0]);
                mma_f16(sacc[2 * jp + 1], qf, &kf4[2]);
            }
        }
        __syncthreads();              // all warps done reading K buffer
        if (more) { load_k(t + 1); CP_COMMIT(); }   // overlap with softmax+PV

        // mask (only boundary tiles) + running max
        if (jb + 64 > q0 || jb + 448 < q0) {
#pragma unroll
            for (int j = 0; j < 8; j++) {
                int kj = jb + 8 * j + 2 * (lane & 3);
                if (!((kj     <= qi0) && (qi0 - kj     < WIN))) sacc[j][0] = -1e30f;
                if (!((kj + 1 <= qi0) && (qi0 - kj - 1 < WIN))) sacc[j][1] = -1e30f;
                if (!((kj     <= qi1) && (qi1 - kj     < WIN))) sacc[j][2] = -1e30f;
                if (!((kj + 1 <= qi1) && (qi1 - kj - 1 < WIN))) sacc[j][3] = -1e30f;
            }
        }
        float mt0 = -1e30f, mt1 = -1e30f;
#pragma unroll
        for (int j = 0; j < 8; j++) {
            mt0 = fmaxf(mt0, fmaxf(sacc[j][0], sacc[j][1]));
            mt1 = fmaxf(mt1, fmaxf(sacc[j][2], sacc[j][3]));
        }
        mt0 = fmaxf(mt0, __shfl_xor_sync(0xffffffffu, mt0, 1));
        mt0 = fmaxf(mt0, __shfl_xor_sync(0xffffffffu, mt0, 2));
        mt1 = fmaxf(mt1, __shfl_xor_sync(0xffffffffu, mt1, 1));
        mt1 = fmaxf(mt1, __shfl_xor_sync(0xffffffffu, mt1, 2));
        float mn0 = fmaxf(m0, mt0), mn1 = fmaxf(m1, mt1);
        float f0 = exp2f(m0 - mn0), f1 = exp2f(m1 - mn1);
        m0 = mn0; m1 = mn1;

        // exp (base-2; guard-free — exp2f(-1e30) underflows to exactly 0,
        // and all-masked-prefix garbage is annihilated by f = 0 later)
        float rs0 = 0.f, rs1 = 0.f;
#pragma unroll
        for (int j = 0; j < 8; j++) {
            sacc[j][0] = exp2f(sacc[j][0] - mn0);
            sacc[j][1] = exp2f(sacc[j][1] - mn0);
            sacc[j][2] = exp2f(sacc[j][2] - mn1);
            sacc[j][3] = exp2f(sacc[j][3] - mn1);
            rs0 += sacc[j][0] + sacc[j][1];
            rs1 += sacc[j][2] + sacc[j][3];
        }
        rs0 += __shfl_xor_sync(0xffffffffu, rs0, 1);
        rs0 += __shfl_xor_sync(0xffffffffu, rs0, 2);
        rs1 += __shfl_xor_sync(0xffffffffu, rs1, 1);
        rs1 += __shfl_xor_sync(0xffffffffu, rs1, 2);
        l0 = l0 * f0 + rs0;
        l1 = l1 * f1 + rs1;

        // rescale O
#pragma unroll
        for (int j = 0; j < 16; j++) {
            o[j][0] *= f0; o[j][1] *= f0;
            o[j][2] *= f1; o[j][3] *= f1;
        }

        // pack P into fp16 A-frags (reg->reg)
        uint32_t pa[4][4];
#pragma unroll
        for (int kch = 0; kch < 4; kch++) {
#pragma unroll
            for (int e = 0; e < 4; e++) {
                int jj = 2 * kch + (e >> 1);
                int b = (e & 1) * 2;
                __half2 ph = __float22half2_rn(make_float2(sacc[jj][b], sacc[jj][b + 1]));
                pa[kch][e] = *(uint32_t*)&ph;
            }
        }

        // wait for V(t): K(t+1) (if issued) remains in flight
        if (more) CP_WAIT(1); else CP_WAIT(0);
        __syncthreads();

        // O += P @ V  (V via paired ldsm_x4)
#pragma unroll
        for (int kch = 0; kch < 4; kch++) {
#pragma unroll
            for (int jp = 0; jp < 8; jp++) {
                uint32_t vf4[4];
                uint32_t va = sb + AT_VH + (16 * jp + prow) * 144 +
                              (2 * kch + phalf) * 16;
                ldsm_x4(vf4, va);
                mma_f16(o[2 * jp],     pa[kch], &vf4[0]);
                mma_f16(o[2 * jp + 1], pa[kch], &vf4[2]);
            }
        }
        __syncthreads();              // all warps done reading V buffer
        if (more) { load_v(t + 1); CP_COMMIT(); }   // overlap with next S
    }

    // epilogue: normalize, store fp16 [s][h*128+d]
    float inv0 = 1.f / l0, inv1 = 1.f / l1;
    size_t r0b = (size_t)qi0 * DMODEL + h * DHEAD;
    size_t r1b = (size_t)qi1 * DMODEL + h * DHEAD;
#pragma unroll
    for (int j = 0; j < 16; j++) {
        int d = 8 * j + 2 * (lane & 3);
        __half2 h0 = __float22half2_rn(make_float2(o[j][0] * inv0, o[j][1] * inv0));
        __half2 h1 = __float22half2_rn(make_float2(o[j][2] * inv1, o[j][3] * inv1));
        *(uint32_t*)&ahi[r0b + d] = *(uint32_t*)&h0;
        *(uint32_t*)&ahi[r1b + d] = *(uint32_t*)&h1;
    }
}

// ---------------------------------------------------------------------------
extern "C" void kernel_launch(void* const* d_in, const int* in_sizes, int n_in,
                              void* d_out, int out_size)
{
    const float* x    = (const float*)d_in[0];
    const float* cosc = (const float*)d_in[1];
    const float* sinc = (const float*)d_in[2];
    // d_in[3] positions (== arange), d_in[4] attn_mask: handled analytically
    const float* Wq = (const float*)d_in[5];
    const float* Wk = (const float*)d_in[6];
    const float* Wv = (const float*)d_in[7];
    const float* Wo = (const float*)d_in[8];
    float* out = (float*)d_out;

    __half *xh, *wt, *wo, *ah;
    cudaGetSymbolAddress((void**)&xh, g_xh);
    cudaGetSymbolAddress((void**)&wt, g_wt);
    cudaGetSymbolAddress((void**)&wo, g_wo);
    cudaGetSymbolAddress((void**)&ah, g_a_hi);

    // 1. merged prep: convert x + transpose all weights (one launch)
    prep_all<<<14336, 256>>>((const float4*)x, xh, Wq, Wk, Wv, Wo, wt, wo);

    cudaFuncSetAttribute(gemm_qkv, cudaFuncAttributeMaxDynamicSharedMemorySize, GS1_SMEM);
    cudaFuncSetAttribute(gemm_mma1, cudaFuncAttributeMaxDynamicSharedMemorySize, GS1_SMEM);
    cudaFuncSetAttribute(attn_tc, cudaFuncAttributeMaxDynamicSharedMemorySize, AT_SMEM);

    // 2. Fused QKV projection + RoPE + scatter
    gemm_qkv<<<dim3(24, 16), 256, GS1_SMEM>>>(xh, wt, cosc, sinc, out);

    // 3. Tensor-core attention (K/V overlap + x4 pairing + mask skip)
    attn_tc<<<dim3(SEQ / 64, NHQ), 128, AT_SMEM>>>(ah);

    // 4. Output projection
    gemm_mma1<<<dim3(16, 16), 256, GS1_SMEM>>>(ah, wo, out, DMODEL);
}